// round 1
// baseline (speedup 1.0000x reference)
#include <cuda_runtime.h>
#include <math.h>
#include <stddef.h>

#define Bc   2
#define Lc   2048
#define Dc   2048
#define Hc   32
#define HKVc 8
#define HDc  64

// Scratch (allocation-free rule: __device__ globals)
__device__ float g_qlin[(size_t)Bc * Lc * Hc * HDc];    // 33.5 MB
__device__ float g_klin[(size_t)Bc * Lc * HKVc * HDc];  // 8.4 MB
__device__ float g_vlin[(size_t)Bc * Lc * HKVc * HDc];  // 8.4 MB
__device__ float g_attn[(size_t)Bc * Lc * Hc * HDc];    // 33.5 MB

// ---------------------------------------------------------------------------
// 128x128x8 fp32 SGEMM, 256 threads, each thread 8x8 (4+4 split) microtile.
// A: MxK row-major, B: KxN row-major, C: MxN row-major. M,N,K % 128/8 == 0.
// ---------------------------------------------------------------------------
__global__ __launch_bounds__(256) void sgemm128(
    const float* __restrict__ A, const float* __restrict__ B,
    float* __restrict__ C, int M, int N, int K)
{
    __shared__ float As[8][128];
    __shared__ float Bs[8][128];

    const int tid = threadIdx.x;
    const int tx = tid & 15;        // 0..15 -> N microtile
    const int ty = tid >> 4;        // 0..15 -> M microtile
    const int row0 = blockIdx.y * 128;
    const int col0 = blockIdx.x * 128;

    // A tile loads: each thread one float4 (128 rows x 8 cols)
    const int arow = tid >> 1;          // 0..127
    const int acol = (tid & 1) * 4;     // 0 or 4
    // B tile loads: each thread one float4 (8 rows x 128 cols)
    const int brow = tid >> 5;          // 0..7
    const int bcol = (tid & 31) * 4;    // 0..124

    const float* Ap = A + (size_t)(row0 + arow) * K + acol;
    const float* Bp = B + (size_t)brow * N + col0 + bcol;

    float acc[8][8];
#pragma unroll
    for (int i = 0; i < 8; i++)
#pragma unroll
        for (int j = 0; j < 8; j++) acc[i][j] = 0.f;

    for (int k0 = 0; k0 < K; k0 += 8) {
        float4 av = *(const float4*)(Ap + k0);
        float4 bv = *(const float4*)(Bp + (size_t)k0 * N);
        As[acol + 0][arow] = av.x;
        As[acol + 1][arow] = av.y;
        As[acol + 2][arow] = av.z;
        As[acol + 3][arow] = av.w;
        *(float4*)&Bs[brow][bcol] = bv;
        __syncthreads();

#pragma unroll
        for (int kk = 0; kk < 8; kk++) {
            float4 a0 = *(const float4*)&As[kk][ty * 4];
            float4 a1 = *(const float4*)&As[kk][64 + ty * 4];
            float4 b0 = *(const float4*)&Bs[kk][tx * 4];
            float4 b1 = *(const float4*)&Bs[kk][64 + tx * 4];
            float a[8] = {a0.x, a0.y, a0.z, a0.w, a1.x, a1.y, a1.z, a1.w};
            float b[8] = {b0.x, b0.y, b0.z, b0.w, b1.x, b1.y, b1.z, b1.w};
#pragma unroll
            for (int i = 0; i < 8; i++)
#pragma unroll
                for (int j = 0; j < 8; j++)
                    acc[i][j] += a[i] * b[j];
        }
        __syncthreads();
    }

#pragma unroll
    for (int i = 0; i < 8; i++) {
        int row = row0 + ((i < 4) ? (ty * 4 + i) : (64 + ty * 4 + i - 4));
        float4 c0 = {acc[i][0], acc[i][1], acc[i][2], acc[i][3]};
        float4 c1 = {acc[i][4], acc[i][5], acc[i][6], acc[i][7]};
        *(float4*)(C + (size_t)row * N + col0 + tx * 4)      = c0;
        *(float4*)(C + (size_t)row * N + col0 + 64 + tx * 4) = c1;
    }
}

// ---------------------------------------------------------------------------
// Fused per-head RMSNorm + RoPE, in place. One warp per (b,l,head) row of 64.
// Row index r = (b*L + l)*nheads + h; pos = l.
// ---------------------------------------------------------------------------
__global__ __launch_bounds__(256) void rmsrope_kernel(
    float* __restrict__ t, const float* __restrict__ w, int nheads, int nrows)
{
    int warp = (blockIdx.x * blockDim.x + threadIdx.x) >> 5;
    int lane = threadIdx.x & 31;
    if (warp >= nrows) return;
    int pos = (warp / nheads) % Lc;

    float* row = t + (size_t)warp * HDc;
    float x1 = row[lane];
    float x2 = row[lane + 32];

    float ss = x1 * x1 + x2 * x2;
#pragma unroll
    for (int o = 16; o > 0; o >>= 1) ss += __shfl_xor_sync(0xffffffffu, ss, o);
    float r = rsqrtf(ss * (1.0f / 64.0f) + 1e-5f);

    float x1n = x1 * r * w[lane];
    float x2n = x2 * r * w[lane + 32];

    // match JAX fp32: inv_freq = theta ** (-(2i)/64), ang = pos * inv_freq
    float expnt = -((float)(2 * lane)) * (1.0f / 64.0f);
    float invf = powf(1000000.0f, expnt);
    float ang = (float)pos * invf;
    float c = cosf(ang);
    float s = sinf(ang);

    row[lane]      = x1n * c - x2n * s;
    row[lane + 32] = x2n * c + x1n * s;
}

// ---------------------------------------------------------------------------
// Flash attention fp32, 64-query x 64-key tiles, HD=64, causal, GQA (g=4).
// Layouts: Q [B,L,H,HD], K/V [B,L,HKV,HD], O [B,L,H,HD].
// 256 threads: thread (qi = tid>>2, sub = tid&3). sub owns keys kk*4+sub and
// output dims i*4+sub (interleaved -> conflict-free smem access, pad 65).
// ---------------------------------------------------------------------------
#define FPAD 65
#define FSM_FLOATS (4 * 64 * FPAD)

__global__ __launch_bounds__(256) void flash64(
    const float* __restrict__ Q, const float* __restrict__ Kp,
    const float* __restrict__ Vp, float* __restrict__ O)
{
    extern __shared__ float sm[];
    float* Qs = sm;
    float* Ks = sm + 64 * FPAD;
    float* Vs = sm + 2 * 64 * FPAD;
    float* Ps = sm + 3 * 64 * FPAD;

    const int tid = threadIdx.x;
    const int qt = blockIdx.x;
    const int h  = blockIdx.y;
    const int b  = blockIdx.z;
    const int hkv = h >> 2;                 // g = H/HKV = 4
    const int qi = tid >> 2;
    const int sub = tid & 3;
    const int qg = qt * 64 + qi;
    const float scale = 0.125f;             // 64^-0.5

    // Load Q tile (64x64): 4 float4 per thread
#pragma unroll
    for (int it = 0; it < 4; it++) {
        int fid = tid + it * 256;           // float4 id 0..1023
        int r = fid >> 4;
        int c4 = (fid & 15) * 4;
        float4 v4 = *(const float4*)(Q + ((size_t)(b * Lc + qt * 64 + r) * Hc + h) * HDc + c4);
        Qs[r * FPAD + c4 + 0] = v4.x;
        Qs[r * FPAD + c4 + 1] = v4.y;
        Qs[r * FPAD + c4 + 2] = v4.z;
        Qs[r * FPAD + c4 + 3] = v4.w;
    }

    float acc[16];
#pragma unroll
    for (int i = 0; i < 16; i++) acc[i] = 0.f;
    float mrow = -INFINITY;
    float lsum = 0.f;

    for (int j = 0; j <= qt; j++) {
        __syncthreads();   // previous iter's smem reads done (also covers Q load)
#pragma unroll
        for (int it = 0; it < 4; it++) {
            int fid = tid + it * 256;
            int r = fid >> 4;
            int c4 = (fid & 15) * 4;
            size_t g = ((size_t)(b * Lc + j * 64 + r) * HKVc + hkv) * HDc + c4;
            float4 kv = *(const float4*)(Kp + g);
            float4 vv = *(const float4*)(Vp + g);
            Ks[r * FPAD + c4 + 0] = kv.x; Ks[r * FPAD + c4 + 1] = kv.y;
            Ks[r * FPAD + c4 + 2] = kv.z; Ks[r * FPAD + c4 + 3] = kv.w;
            Vs[r * FPAD + c4 + 0] = vv.x; Vs[r * FPAD + c4 + 1] = vv.y;
            Vs[r * FPAD + c4 + 2] = vv.z; Vs[r * FPAD + c4 + 3] = vv.w;
        }
        __syncthreads();

        // S = Q K^T for 16 keys (kk*4+sub)
        float s[16];
#pragma unroll
        for (int kk = 0; kk < 16; kk++) s[kk] = 0.f;
        for (int d = 0; d < 64; d++) {
            float qd = Qs[qi * FPAD + d];
#pragma unroll
            for (int kk = 0; kk < 16; kk++)
                s[kk] += qd * Ks[(kk * 4 + sub) * FPAD + d];
        }

        // scale + causal mask + tile max
        float tmax = -INFINITY;
#pragma unroll
        for (int kk = 0; kk < 16; kk++) {
            float sv = s[kk] * scale;
            int kgl = j * 64 + kk * 4 + sub;
            if (kgl > qg) sv = -INFINITY;
            s[kk] = sv;
            tmax = fmaxf(tmax, sv);
        }
        tmax = fmaxf(tmax, __shfl_xor_sync(0xffffffffu, tmax, 1));
        tmax = fmaxf(tmax, __shfl_xor_sync(0xffffffffu, tmax, 2));

        float mnew = fmaxf(mrow, tmax);
        float corr = expf(mrow - mnew);   // exp(-inf)=0 on first tile

        float psum = 0.f;
#pragma unroll
        for (int kk = 0; kk < 16; kk++) {
            float p = expf(s[kk] - mnew);
            Ps[qi * FPAD + kk * 4 + sub] = p;
            psum += p;
        }
        psum += __shfl_xor_sync(0xffffffffu, psum, 1);
        psum += __shfl_xor_sync(0xffffffffu, psum, 2);

        lsum = lsum * corr + psum;
#pragma unroll
        for (int i = 0; i < 16; i++) acc[i] *= corr;
        __syncwarp();

        // acc += P @ V  (dims i*4+sub)
        for (int kk2 = 0; kk2 < 64; kk2++) {
            float p = Ps[qi * FPAD + kk2];
#pragma unroll
            for (int i = 0; i < 16; i++)
                acc[i] += p * Vs[kk2 * FPAD + i * 4 + sub];
        }
        mrow = mnew;
    }

    float inv = 1.f / lsum;
    size_t ob = ((size_t)(b * Lc + qg) * Hc + h) * HDc;
#pragma unroll
    for (int i = 0; i < 16; i++)
        O[ob + i * 4 + sub] = acc[i] * inv;
}

// ---------------------------------------------------------------------------
extern "C" void kernel_launch(void* const* d_in, const int* in_sizes, int n_in,
                              void* d_out, int out_size)
{
    const float* x   = (const float*)d_in[0];
    const float* Wq  = (const float*)d_in[1];
    const float* Wk  = (const float*)d_in[2];
    const float* Wv  = (const float*)d_in[3];
    const float* Wo  = (const float*)d_in[4];
    const float* qnw = (const float*)d_in[5];
    const float* knw = (const float*)d_in[6];
    float* out = (float*)d_out;

    float *qlin, *klin, *vlin, *attn;
    cudaGetSymbolAddress((void**)&qlin, g_qlin);
    cudaGetSymbolAddress((void**)&klin, g_klin);
    cudaGetSymbolAddress((void**)&vlin, g_vlin);
    cudaGetSymbolAddress((void**)&attn, g_attn);

    const int M = Bc * Lc;            // 4096

    // QKV projections
    sgemm128<<<dim3((Hc * HDc) / 128, M / 128), 256>>>(x, Wq, qlin, M, Hc * HDc, Dc);
    sgemm128<<<dim3((HKVc * HDc) / 128, M / 128), 256>>>(x, Wk, klin, M, HKVc * HDc, Dc);
    sgemm128<<<dim3((HKVc * HDc) / 128, M / 128), 256>>>(x, Wv, vlin, M, HKVc * HDc, Dc);

    // RMSNorm + RoPE (in place)
    rmsrope_kernel<<<(Bc * Lc * Hc) / 8, 256>>>(qlin, qnw, Hc, Bc * Lc * Hc);
    rmsrope_kernel<<<(Bc * Lc * HKVc) / 8, 256>>>(klin, knw, HKVc, Bc * Lc * HKVc);

    // Flash attention
    const int smem_bytes = FSM_FLOATS * (int)sizeof(float);   // 66,560 B
    cudaFuncSetAttribute(flash64, cudaFuncAttributeMaxDynamicSharedMemorySize, smem_bytes);
    flash64<<<dim3(Lc / 64, Hc, Bc), 256, smem_bytes>>>(qlin, klin, vlin, attn);

    // Output projection
    sgemm128<<<dim3(Dc / 128, M / 128), 256>>>(attn, Wo, out, M, Dc, Dc);
}

// round 2
// speedup vs baseline: 1.0743x; 1.0743x over previous
#include <cuda_runtime.h>
#include <cuda_bf16.h>
#include <math.h>
#include <stddef.h>
#include <stdint.h>

#define Bc   2
#define Lc   2048
#define Dc   2048
#define Hc   32
#define HKVc 8
#define HDc  64

// Scratch (allocation-free rule: __device__ globals)
__device__ float g_qlin[(size_t)Bc * Lc * Hc * HDc];    // 33.5 MB
__device__ float g_klin[(size_t)Bc * Lc * HKVc * HDc];  // 8.4 MB
__device__ float g_vlin[(size_t)Bc * Lc * HKVc * HDc];  // 8.4 MB
__device__ float g_attn[(size_t)Bc * Lc * Hc * HDc];    // 33.5 MB

// ---------------------------------------------------------------------------
// Tensor-core GEMM: fp32 in/out, internally split-bf16 (Markidis 3-mma).
// C = A @ B.  A: MxK row-major fp32, B: KxN row-major fp32, C: MxN fp32.
// Block tile 128x128x32, 256 threads (8 warps, each 32x64 warp tile).
// mma.sync.aligned.m16n8k16.row.col.f32.bf16.bf16.f32
// ---------------------------------------------------------------------------
#define BM 128
#define BN 128
#define BK 32
#define LDT (BK + 8)   // 40 elems: fragment loads hit all 32 banks conflict-free

#define MMA_BF16(cr, a, b0, b1)                                              \
  asm volatile(                                                              \
      "mma.sync.aligned.m16n8k16.row.col.f32.bf16.bf16.f32 "                 \
      "{%0,%1,%2,%3},{%4,%5,%6,%7},{%8,%9},{%0,%1,%2,%3};"                   \
      : "+f"(cr[0]), "+f"(cr[1]), "+f"(cr[2]), "+f"(cr[3])                   \
      : "r"(a[0]), "r"(a[1]), "r"(a[2]), "r"(a[3]), "r"(b0), "r"(b1));

__global__ __launch_bounds__(256) void gemm_tc(
    const float* __restrict__ A, const float* __restrict__ Bg,
    float* __restrict__ C, int M, int N, int K)
{
    __shared__ __nv_bfloat16 Ah[BM][LDT], Al[BM][LDT];
    __shared__ __nv_bfloat16 Bh[BN][LDT], Bl[BN][LDT];   // transposed: [n][k]

    const int tid  = threadIdx.x;
    const int lane = tid & 31;
    const int warp = tid >> 5;
    const int wm = (warp & 3) * 32;   // warp M offset
    const int wn = (warp >> 2) * 64;  // warp N offset
    const int g  = lane >> 2;         // 0..7
    const int t  = lane & 3;          // 0..3
    const int row0 = blockIdx.y * BM;
    const int col0 = blockIdx.x * BN;

    float cacc[2][8][4];
#pragma unroll
    for (int i = 0; i < 2; i++)
#pragma unroll
        for (int j = 0; j < 8; j++)
#pragma unroll
            for (int e = 0; e < 4; e++) cacc[i][j][e] = 0.f;

    float4 abuf[4], bbuf[4];

    // prefetch first K-slab
#pragma unroll
    for (int it = 0; it < 4; it++) {
        int fid = tid + it * 256;
        int ar = fid >> 3, ac = (fid & 7) * 4;
        abuf[it] = *(const float4*)(A + (size_t)(row0 + ar) * K + ac);
        int bk = fid >> 5, bn = (fid & 31) * 4;
        bbuf[it] = *(const float4*)(Bg + (size_t)bk * N + col0 + bn);
    }

    for (int k0 = 0; k0 < K; k0 += BK) {
        // stage + split-convert into smem
#pragma unroll
        for (int it = 0; it < 4; it++) {
            int fid = tid + it * 256;
            int ar = fid >> 3, ac = (fid & 7) * 4;
            float va[4] = {abuf[it].x, abuf[it].y, abuf[it].z, abuf[it].w};
#pragma unroll
            for (int e = 0; e < 4; e++) {
                __nv_bfloat16 h = __float2bfloat16_rn(va[e]);
                Ah[ar][ac + e] = h;
                Al[ar][ac + e] = __float2bfloat16_rn(va[e] - __bfloat162float(h));
            }
            int bk = fid >> 5, bn = (fid & 31) * 4;
            float vb[4] = {bbuf[it].x, bbuf[it].y, bbuf[it].z, bbuf[it].w};
#pragma unroll
            for (int e = 0; e < 4; e++) {
                __nv_bfloat16 h = __float2bfloat16_rn(vb[e]);
                Bh[bn + e][bk] = h;
                Bl[bn + e][bk] = __float2bfloat16_rn(vb[e] - __bfloat162float(h));
            }
        }
        __syncthreads();

        // prefetch next slab (hidden under mma work)
        if (k0 + BK < K) {
#pragma unroll
            for (int it = 0; it < 4; it++) {
                int fid = tid + it * 256;
                int ar = fid >> 3, ac = (fid & 7) * 4;
                abuf[it] = *(const float4*)(A + (size_t)(row0 + ar) * K + k0 + BK + ac);
                int bk = fid >> 5, bn = (fid & 31) * 4;
                bbuf[it] = *(const float4*)(Bg + (size_t)(k0 + BK + bk) * N + col0 + bn);
            }
        }

#pragma unroll
        for (int ch = 0; ch < 2; ch++) {
            const int kc = ch * 16;
            uint32_t ah[2][4], al[2][4];
#pragma unroll
            for (int mt = 0; mt < 2; mt++) {
                int r = wm + mt * 16 + g;
                ah[mt][0] = *(const uint32_t*)&Ah[r][kc + 2 * t];
                ah[mt][1] = *(const uint32_t*)&Ah[r + 8][kc + 2 * t];
                ah[mt][2] = *(const uint32_t*)&Ah[r][kc + 8 + 2 * t];
                ah[mt][3] = *(const uint32_t*)&Ah[r + 8][kc + 8 + 2 * t];
                al[mt][0] = *(const uint32_t*)&Al[r][kc + 2 * t];
                al[mt][1] = *(const uint32_t*)&Al[r + 8][kc + 2 * t];
                al[mt][2] = *(const uint32_t*)&Al[r][kc + 8 + 2 * t];
                al[mt][3] = *(const uint32_t*)&Al[r + 8][kc + 8 + 2 * t];
            }
#pragma unroll
            for (int nt = 0; nt < 8; nt++) {
                int nr = wn + nt * 8 + g;
                uint32_t bh0 = *(const uint32_t*)&Bh[nr][kc + 2 * t];
                uint32_t bh1 = *(const uint32_t*)&Bh[nr][kc + 8 + 2 * t];
                uint32_t bl0 = *(const uint32_t*)&Bl[nr][kc + 2 * t];
                uint32_t bl1 = *(const uint32_t*)&Bl[nr][kc + 8 + 2 * t];
#pragma unroll
                for (int mt = 0; mt < 2; mt++) {
                    MMA_BF16(cacc[mt][nt], ah[mt], bh0, bh1);
                    MMA_BF16(cacc[mt][nt], ah[mt], bl0, bl1);
                    MMA_BF16(cacc[mt][nt], al[mt], bh0, bh1);
                }
            }
        }
        __syncthreads();
    }

    // epilogue
#pragma unroll
    for (int mt = 0; mt < 2; mt++) {
#pragma unroll
        for (int nt = 0; nt < 8; nt++) {
            int r = row0 + wm + mt * 16 + g;
            int cc = col0 + wn + nt * 8 + 2 * t;
            float2 v0 = {cacc[mt][nt][0], cacc[mt][nt][1]};
            float2 v1 = {cacc[mt][nt][2], cacc[mt][nt][3]};
            *(float2*)(C + (size_t)r * N + cc) = v0;
            *(float2*)(C + (size_t)(r + 8) * N + cc) = v1;
        }
    }
}

// ---------------------------------------------------------------------------
// Fused per-head RMSNorm + RoPE, in place. One warp per (b,l,head) row of 64.
// ---------------------------------------------------------------------------
__global__ __launch_bounds__(256) void rmsrope_kernel(
    float* __restrict__ t, const float* __restrict__ w, int nheads, int nrows)
{
    int warp = (blockIdx.x * blockDim.x + threadIdx.x) >> 5;
    int lane = threadIdx.x & 31;
    if (warp >= nrows) return;
    int pos = (warp / nheads) % Lc;

    float* row = t + (size_t)warp * HDc;
    float x1 = row[lane];
    float x2 = row[lane + 32];

    float ss = x1 * x1 + x2 * x2;
#pragma unroll
    for (int o = 16; o > 0; o >>= 1) ss += __shfl_xor_sync(0xffffffffu, ss, o);
    float r = rsqrtf(ss * (1.0f / 64.0f) + 1e-5f);

    float x1n = x1 * r * w[lane];
    float x2n = x2 * r * w[lane + 32];

    float expnt = -((float)(2 * lane)) * (1.0f / 64.0f);
    float invf = powf(1000000.0f, expnt);
    float ang = (float)pos * invf;
    float c = cosf(ang);
    float s = sinf(ang);

    row[lane]      = x1n * c - x2n * s;
    row[lane + 32] = x2n * c + x1n * s;
}

// ---------------------------------------------------------------------------
// Flash attention fp32, 64x64 tiles, HD=64, causal, GQA (g=4).
// ---------------------------------------------------------------------------
#define FPAD 65
#define FSM_FLOATS (4 * 64 * FPAD)

__global__ __launch_bounds__(256) void flash64(
    const float* __restrict__ Q, const float* __restrict__ Kp,
    const float* __restrict__ Vp, float* __restrict__ O)
{
    extern __shared__ float sm[];
    float* Qs = sm;
    float* Ks = sm + 64 * FPAD;
    float* Vs = sm + 2 * 64 * FPAD;
    float* Ps = sm + 3 * 64 * FPAD;

    const int tid = threadIdx.x;
    const int qt = blockIdx.x;
    const int h  = blockIdx.y;
    const int b  = blockIdx.z;
    const int hkv = h >> 2;
    const int qi = tid >> 2;
    const int sub = tid & 3;
    const int qg = qt * 64 + qi;
    const float scale = 0.125f;

#pragma unroll
    for (int it = 0; it < 4; it++) {
        int fid = tid + it * 256;
        int r = fid >> 4;
        int c4 = (fid & 15) * 4;
        float4 v4 = *(const float4*)(Q + ((size_t)(b * Lc + qt * 64 + r) * Hc + h) * HDc + c4);
        Qs[r * FPAD + c4 + 0] = v4.x;
        Qs[r * FPAD + c4 + 1] = v4.y;
        Qs[r * FPAD + c4 + 2] = v4.z;
        Qs[r * FPAD + c4 + 3] = v4.w;
    }

    float acc[16];
#pragma unroll
    for (int i = 0; i < 16; i++) acc[i] = 0.f;
    float mrow = -INFINITY;
    float lsum = 0.f;

    for (int j = 0; j <= qt; j++) {
        __syncthreads();
#pragma unroll
        for (int it = 0; it < 4; it++) {
            int fid = tid + it * 256;
            int r = fid >> 4;
            int c4 = (fid & 15) * 4;
            size_t gk = ((size_t)(b * Lc + j * 64 + r) * HKVc + hkv) * HDc + c4;
            float4 kv = *(const float4*)(Kp + gk);
            float4 vv = *(const float4*)(Vp + gk);
            Ks[r * FPAD + c4 + 0] = kv.x; Ks[r * FPAD + c4 + 1] = kv.y;
            Ks[r * FPAD + c4 + 2] = kv.z; Ks[r * FPAD + c4 + 3] = kv.w;
            Vs[r * FPAD + c4 + 0] = vv.x; Vs[r * FPAD + c4 + 1] = vv.y;
            Vs[r * FPAD + c4 + 2] = vv.z; Vs[r * FPAD + c4 + 3] = vv.w;
        }
        __syncthreads();

        float s[16];
#pragma unroll
        for (int kk = 0; kk < 16; kk++) s[kk] = 0.f;
        for (int d = 0; d < 64; d++) {
            float qd = Qs[qi * FPAD + d];
#pragma unroll
            for (int kk = 0; kk < 16; kk++)
                s[kk] += qd * Ks[(kk * 4 + sub) * FPAD + d];
        }

        float tmax = -INFINITY;
#pragma unroll
        for (int kk = 0; kk < 16; kk++) {
            float sv = s[kk] * scale;
            int kgl = j * 64 + kk * 4 + sub;
            if (kgl > qg) sv = -INFINITY;
            s[kk] = sv;
            tmax = fmaxf(tmax, sv);
        }
        tmax = fmaxf(tmax, __shfl_xor_sync(0xffffffffu, tmax, 1));
        tmax = fmaxf(tmax, __shfl_xor_sync(0xffffffffu, tmax, 2));

        float mnew = fmaxf(mrow, tmax);
        float corr = expf(mrow - mnew);

        float psum = 0.f;
#pragma unroll
        for (int kk = 0; kk < 16; kk++) {
            float p = expf(s[kk] - mnew);
            Ps[qi * FPAD + kk * 4 + sub] = p;
            psum += p;
        }
        psum += __shfl_xor_sync(0xffffffffu, psum, 1);
        psum += __shfl_xor_sync(0xffffffffu, psum, 2);

        lsum = lsum * corr + psum;
#pragma unroll
        for (int i = 0; i < 16; i++) acc[i] *= corr;
        __syncwarp();

        for (int kk2 = 0; kk2 < 64; kk2++) {
            float p = Ps[qi * FPAD + kk2];
#pragma unroll
            for (int i = 0; i < 16; i++)
                acc[i] += p * Vs[kk2 * FPAD + i * 4 + sub];
        }
        mrow = mnew;
    }

    float inv = 1.f / lsum;
    size_t ob = ((size_t)(b * Lc + qg) * Hc + h) * HDc;
#pragma unroll
    for (int i = 0; i < 16; i++)
        O[ob + i * 4 + sub] = acc[i] * inv;
}

// ---------------------------------------------------------------------------
extern "C" void kernel_launch(void* const* d_in, const int* in_sizes, int n_in,
                              void* d_out, int out_size)
{
    const float* x   = (const float*)d_in[0];
    const float* Wq  = (const float*)d_in[1];
    const float* Wk  = (const float*)d_in[2];
    const float* Wv  = (const float*)d_in[3];
    const float* Wo  = (const float*)d_in[4];
    const float* qnw = (const float*)d_in[5];
    const float* knw = (const float*)d_in[6];
    float* out = (float*)d_out;

    float *qlin, *klin, *vlin, *attn;
    cudaGetSymbolAddress((void**)&qlin, g_qlin);
    cudaGetSymbolAddress((void**)&klin, g_klin);
    cudaGetSymbolAddress((void**)&vlin, g_vlin);
    cudaGetSymbolAddress((void**)&attn, g_attn);

    const int M = Bc * Lc;            // 4096

    gemm_tc<<<dim3((Hc * HDc) / BN, M / BM), 256>>>(x, Wq, qlin, M, Hc * HDc, Dc);
    gemm_tc<<<dim3((HKVc * HDc) / BN, M / BM), 256>>>(x, Wk, klin, M, HKVc * HDc, Dc);
    gemm_tc<<<dim3((HKVc * HDc) / BN, M / BM), 256>>>(x, Wv, vlin, M, HKVc * HDc, Dc);

    rmsrope_kernel<<<(Bc * Lc * Hc) / 8, 256>>>(qlin, qnw, Hc, Bc * Lc * Hc);
    rmsrope_kernel<<<(Bc * Lc * HKVc) / 8, 256>>>(klin, knw, HKVc, Bc * Lc * HKVc);

    const int smem_bytes = FSM_FLOATS * (int)sizeof(float);
    cudaFuncSetAttribute(flash64, cudaFuncAttributeMaxDynamicSharedMemorySize, smem_bytes);
    flash64<<<dim3(Lc / 64, Hc, Bc), 256, smem_bytes>>>(qlin, klin, vlin, attn);

    gemm_tc<<<dim3(Dc / BN, M / BM), 256>>>(attn, Wo, out, M, Dc, Dc);
}

// round 3
// speedup vs baseline: 4.8592x; 4.5232x over previous
#include <cuda_runtime.h>
#include <cuda_bf16.h>
#include <math.h>
#include <stdint.h>
#include <stddef.h>

#define Bc 2
#define Lc 2048
#define Dc 2048
#define Hc 32
#define HKVc 8
#define HDc 64
#define Mtok (Bc*Lc)

typedef __nv_bfloat16 bf16;
typedef __nv_bfloat162 bf162;

// ---------------- scratch (__device__ globals; no allocs allowed) -----------
__device__ float g_qlin[(size_t)Mtok*Hc*HDc];
__device__ float g_klin[(size_t)Mtok*HKVc*HDc];
__device__ float g_vlin[(size_t)Mtok*HKVc*HDc];

__device__ __align__(16) bf16 g_xh[(size_t)Mtok*Dc];
__device__ __align__(16) bf16 g_xl[(size_t)Mtok*Dc];
__device__ __align__(16) bf16 g_wqT_h[(size_t)Dc*Hc*HDc];
__device__ __align__(16) bf16 g_wqT_l[(size_t)Dc*Hc*HDc];
__device__ __align__(16) bf16 g_wkT_h[(size_t)Dc*HKVc*HDc];
__device__ __align__(16) bf16 g_wkT_l[(size_t)Dc*HKVc*HDc];
__device__ __align__(16) bf16 g_wvT_h[(size_t)Dc*HKVc*HDc];
__device__ __align__(16) bf16 g_wvT_l[(size_t)Dc*HKVc*HDc];
__device__ __align__(16) bf16 g_woT_h[(size_t)Dc*Hc*HDc];
__device__ __align__(16) bf16 g_woT_l[(size_t)Dc*Hc*HDc];
__device__ __align__(16) bf16 g_qh[(size_t)Bc*Hc*Lc*HDc];
__device__ __align__(16) bf16 g_ql[(size_t)Bc*Hc*Lc*HDc];
__device__ __align__(16) bf16 g_kh[(size_t)Bc*HKVc*Lc*HDc];
__device__ __align__(16) bf16 g_kl[(size_t)Bc*HKVc*Lc*HDc];
__device__ __align__(16) bf16 g_vh[(size_t)Bc*HKVc*Lc*HDc];
__device__ __align__(16) bf16 g_vl[(size_t)Bc*HKVc*Lc*HDc];
__device__ __align__(16) bf16 g_ath[(size_t)Mtok*Hc*HDc];
__device__ __align__(16) bf16 g_atl[(size_t)Mtok*Hc*HDc];

// ---------------- PTX helpers ----------------------------------------------
#define MMA4(CR, A, B0, B1)                                                  \
  asm volatile(                                                              \
      "mma.sync.aligned.m16n8k16.row.col.f32.bf16.bf16.f32 "                 \
      "{%0,%1,%2,%3},{%4,%5,%6,%7},{%8,%9},{%0,%1,%2,%3};"                   \
      : "+f"((CR)[0]), "+f"((CR)[1]), "+f"((CR)[2]), "+f"((CR)[3])           \
      : "r"((A)[0]), "r"((A)[1]), "r"((A)[2]), "r"((A)[3]), "r"(B0), "r"(B1))

#define LDSM4(R0,R1,R2,R3,ADDR)                                              \
  asm volatile("ldmatrix.sync.aligned.m8n8.x4.shared.b16 {%0,%1,%2,%3},[%4];"\
      : "=r"(R0),"=r"(R1),"=r"(R2),"=r"(R3) : "r"(ADDR))

#define LDSM4T(R0,R1,R2,R3,ADDR)                                             \
  asm volatile("ldmatrix.sync.aligned.m8n8.x4.trans.shared.b16 {%0,%1,%2,%3},[%4];"\
      : "=r"(R0),"=r"(R1),"=r"(R2),"=r"(R3) : "r"(ADDR))

__device__ __forceinline__ void cp16(uint32_t dst, const void* src){
  asm volatile("cp.async.cg.shared.global [%0], [%1], 16;" :: "r"(dst), "l"(src));
}
#define CPCOMMIT() asm volatile("cp.async.commit_group;")
#define CPWAIT0()  asm volatile("cp.async.wait_group 0;")

__device__ __forceinline__ uint32_t packbf(float a, float b){
  bf162 p; p.x = __float2bfloat16_rn(a); p.y = __float2bfloat16_rn(b);
  return *(uint32_t*)&p;
}
__device__ __forceinline__ void split1(float v, bf16& h, bf16& l){
  h = __float2bfloat16_rn(v);
  l = __float2bfloat16_rn(v - __bfloat162float(h));
}

// ---------------- convert passes --------------------------------------------
__global__ void splitx(const float* __restrict__ src, bf16* __restrict__ h,
                       bf16* __restrict__ l, int n4)
{
  int i = blockIdx.x * blockDim.x + threadIdx.x;
  if (i >= n4) return;
  float4 v = ((const float4*)src)[i];
  bf16 hh[4], ll[4];
  split1(v.x, hh[0], ll[0]); split1(v.y, hh[1], ll[1]);
  split1(v.z, hh[2], ll[2]); split1(v.w, hh[3], ll[3]);
  bf162 h0; h0.x=hh[0]; h0.y=hh[1];  bf162 h1; h1.x=hh[2]; h1.y=hh[3];
  bf162 l0; l0.x=ll[0]; l0.y=ll[1];  bf162 l1; l1.x=ll[2]; l1.y=ll[3];
  ((bf162*)h)[2*i] = h0; ((bf162*)h)[2*i+1] = h1;
  ((bf162*)l)[2*i] = l0; ((bf162*)l)[2*i+1] = l1;
}

// W [K][N] -> Th/Tl [N][K]
__global__ void wsplitT(const float* __restrict__ W, bf16* __restrict__ Th,
                        bf16* __restrict__ Tl, int K, int N)
{
  __shared__ float tile[32][33];
  int k0 = blockIdx.y*32, n0 = blockIdx.x*32;
  int tx = threadIdx.x, ty = threadIdx.y;
#pragma unroll
  for (int i = 0; i < 4; i++)
    tile[ty + 8*i][tx] = W[(size_t)(k0 + ty + 8*i) * N + n0 + tx];
  __syncthreads();
#pragma unroll
  for (int i = 0; i < 4; i++){
    int n = n0 + ty + 8*i;
    float v = tile[tx][ty + 8*i];
    bf16 h, l; split1(v, h, l);
    Th[(size_t)n*K + k0 + tx] = h;
    Tl[(size_t)n*K + k0 + tx] = l;
  }
}

// ---------------- split-bf16 tensor-core GEMM -------------------------------
// C[M][N] fp32 = (Ah+Al)[M][K] @ (Bh+Bl)^T, B stored [N][K]. BK=64.
// 256 thr, 8 warps, warp tile 32x64, cp.async double buffer, swizzled smem.
__global__ __launch_bounds__(256) void gemm_split(
    const bf16* __restrict__ Ah, const bf16* __restrict__ Al,
    const bf16* __restrict__ Bh, const bf16* __restrict__ Bl,
    float* __restrict__ C, int M, int N, int K)
{
  extern __shared__ char smraw[];
  const uint32_t smb = (uint32_t)__cvta_generic_to_shared(smraw);
  const int tid = threadIdx.x, lane = tid & 31, warp = tid >> 5;
  const int wm = (warp & 3) * 32, wn = (warp >> 2) * 64;
  const int g = lane >> 2, t = lane & 3;
  const int row0 = blockIdx.y * 128, col0 = blockIdx.x * 128;
  const int KI = K >> 6;

  const bf16* gsrc[4] = { Ah + (size_t)row0 * K, Al + (size_t)row0 * K,
                          Bh + (size_t)col0 * K, Bl + (size_t)col0 * K };

  auto stage = [&](int ki, int s){
#pragma unroll
    for (int q = 0; q < 4; q++)
#pragma unroll
      for (int it = 0; it < 4; it++){
        int fid = tid + it * 256;
        int row = fid >> 3, ch = fid & 7;
        cp16(smb + s*65536 + q*16384 + row*128 + ((ch ^ (row & 7)) * 16),
             gsrc[q] + (size_t)row * K + ki*64 + ch*8);
      }
  };

  float c[2][8][4];
#pragma unroll
  for (int i=0;i<2;i++)
#pragma unroll
    for (int j=0;j<8;j++)
#pragma unroll
      for (int e=0;e<4;e++) c[i][j][e] = 0.f;

  stage(0, 0); CPCOMMIT();

  for (int ki = 0; ki < KI; ki++){
    int s = ki & 1;
    CPWAIT0();
    __syncthreads();
    if (ki + 1 < KI){ stage(ki + 1, s ^ 1); CPCOMMIT(); }

    const uint32_t ab = smb + s*65536, bb = ab + 32768;
    const int rA  = (lane & 7) + ((lane >> 3) & 1) * 8;
    const int chA = (lane >> 4);
    const int rB  = (lane & 7) + ((lane >> 4) << 3);
    const int chB = (lane >> 3) & 1;
#pragma unroll
    for (int kc = 0; kc < 4; kc++){
      uint32_t ah[2][4], al[2][4];
#pragma unroll
      for (int mt = 0; mt < 2; mt++){
        int r = wm + mt*16 + rA;
        int ch = kc*2 + chA;
        uint32_t ad = ab + r*128 + ((ch ^ (r & 7)) * 16);
        LDSM4(ah[mt][0], ah[mt][1], ah[mt][2], ah[mt][3], ad);
        LDSM4(al[mt][0], al[mt][1], al[mt][2], al[mt][3], ad + 16384);
      }
#pragma unroll
      for (int ntp = 0; ntp < 4; ntp++){
        int r = wn + ntp*16 + rB;
        int ch = kc*2 + chB;
        uint32_t ad = bb + r*128 + ((ch ^ (r & 7)) * 16);
        uint32_t bh0,bh1,bh2,bh3, bl0,bl1,bl2,bl3;
        LDSM4(bh0,bh1,bh2,bh3, ad);
        LDSM4(bl0,bl1,bl2,bl3, ad + 16384);
#pragma unroll
        for (int mt = 0; mt < 2; mt++){
          MMA4(c[mt][2*ntp],   ah[mt], bh0, bh1);
          MMA4(c[mt][2*ntp+1], ah[mt], bh2, bh3);
          MMA4(c[mt][2*ntp],   ah[mt], bl0, bl1);
          MMA4(c[mt][2*ntp+1], ah[mt], bl2, bl3);
          MMA4(c[mt][2*ntp],   al[mt], bh0, bh1);
          MMA4(c[mt][2*ntp+1], al[mt], bh2, bh3);
        }
      }
    }
    __syncthreads();
  }

#pragma unroll
  for (int mt = 0; mt < 2; mt++)
#pragma unroll
    for (int nt = 0; nt < 8; nt++){
      int r = row0 + wm + mt*16 + g;
      int cc = col0 + wn + nt*8 + 2*t;
      float2 v0 = { c[mt][nt][0], c[mt][nt][1] };
      float2 v1 = { c[mt][nt][2], c[mt][nt][3] };
      *(float2*)(C + (size_t)r * N + cc) = v0;
      *(float2*)(C + (size_t)(r + 8) * N + cc) = v1;
    }
}

// ---------------- RMSNorm + RoPE -> split bf16, head-major ------------------
__global__ __launch_bounds__(256) void rmsrope_split(
    const float* __restrict__ lin, const float* __restrict__ w,
    bf16* __restrict__ oh, bf16* __restrict__ ol, int nh, int nrows)
{
  int wid = (blockIdx.x * blockDim.x + threadIdx.x) >> 5;
  int lane = threadIdx.x & 31;
  if (wid >= nrows) return;
  int head = wid % nh;
  int bl = wid / nh;
  int pos = bl % Lc;
  int b = bl / Lc;

  const float* row = lin + (size_t)wid * HDc;
  float x1 = row[lane], x2 = row[lane + 32];

  float ss = x1*x1 + x2*x2;
#pragma unroll
  for (int o = 16; o > 0; o >>= 1) ss += __shfl_xor_sync(0xffffffffu, ss, o);
  float r = rsqrtf(ss * (1.0f/64.0f) + 1e-5f);

  float x1n = x1 * r * w[lane];
  float x2n = x2 * r * w[lane + 32];

  float expnt = -((float)(2*lane)) * (1.0f/64.0f);
  float invf = powf(1000000.0f, expnt);
  float ang = (float)pos * invf;
  float cth = cosf(ang), sth = sinf(ang);

  float y1 = x1n*cth - x2n*sth;
  float y2 = x2n*cth + x1n*sth;

  size_t ob = ((size_t)(b*nh + head)*Lc + pos) * HDc;
  bf16 h, l;
  split1(y1, h, l); oh[ob + lane] = h;      ol[ob + lane] = l;
  split1(y2, h, l); oh[ob + lane + 32] = h; ol[ob + lane + 32] = l;
}

__global__ __launch_bounds__(256) void vsplit_kernel(
    const float* __restrict__ lin, bf16* __restrict__ oh, bf16* __restrict__ ol,
    int nrows)
{
  int wid = (blockIdx.x * blockDim.x + threadIdx.x) >> 5;
  int lane = threadIdx.x & 31;
  if (wid >= nrows) return;
  int head = wid % HKVc;
  int bl = wid / HKVc;
  int pos = bl % Lc;
  int b = bl / Lc;
  const float* row = lin + (size_t)wid * HDc;
  size_t ob = ((size_t)(b*HKVc + head)*Lc + pos) * HDc;
  bf16 h, l;
  split1(row[lane],      h, l); oh[ob + lane] = h;      ol[ob + lane] = l;
  split1(row[lane + 32], h, l); oh[ob + lane + 32] = h; ol[ob + lane + 32] = l;
}

// ---------------- tensor-core flash attention -------------------------------
// block = (qt, h, b), 128 threads (4 warps, 16 q-rows each). 64x64 tiles.
#define FSM_Q   0
#define FSM_KV  16384
#define KV_STG  32768
#define FLASH_SMEM (16384 + 2*32768)

__global__ __launch_bounds__(128) void flash_tc(
    const bf16* __restrict__ Qh, const bf16* __restrict__ Ql,
    const bf16* __restrict__ Kh, const bf16* __restrict__ Kl,
    const bf16* __restrict__ Vh, const bf16* __restrict__ Vl,
    bf16* __restrict__ Oh, bf16* __restrict__ Ol)
{
  extern __shared__ char smraw[];
  const uint32_t smb = (uint32_t)__cvta_generic_to_shared(smraw);
  const int tid = threadIdx.x, lane = tid & 31, warp = tid >> 5;
  const int qt = gridDim.x - 1 - blockIdx.x;   // big tiles first
  const int h = blockIdx.y, b = blockIdx.z, hkv = h >> 2;
  const int g = lane >> 2, t = lane & 3;

  const bf16* qhp = Qh + ((size_t)(b*Hc + h)*Lc + qt*64) * HDc;
  const bf16* qlp = Ql + ((size_t)(b*Hc + h)*Lc + qt*64) * HDc;
  const size_t kvoff = (size_t)(b*HKVc + hkv) * Lc * HDc;
  const bf16* kvsrc[4] = { Kh + kvoff, Kl + kvoff, Vh + kvoff, Vl + kvoff };

  // stage Q (once)
#pragma unroll
  for (int it = 0; it < 4; it++){
    int fid = tid + it * 128;
    int row = fid >> 3, ch = fid & 7;
    uint4 vh4 = *(const uint4*)(qhp + row*64 + ch*8);
    uint4 vl4 = *(const uint4*)(qlp + row*64 + ch*8);
    int off = row*128 + ((ch ^ (row & 7)) * 16);
    *(uint4*)(smraw + FSM_Q + off)        = vh4;
    *(uint4*)(smraw + FSM_Q + 8192 + off) = vl4;
  }

  auto stageKV = [&](int j, int s){
#pragma unroll
    for (int q = 0; q < 4; q++)
#pragma unroll
      for (int it = 0; it < 4; it++){
        int fid = tid + it * 128;
        int row = fid >> 3, ch = fid & 7;
        cp16(smb + FSM_KV + s*KV_STG + q*8192 + row*128 + ((ch ^ (row & 7))*16),
             kvsrc[q] + (size_t)(j*64 + row)*64 + ch*8);
      }
  };

  stageKV(0, 0); CPCOMMIT();
  __syncthreads();

  // Q fragments (persistent)
  uint32_t qfh[4][4], qfl[4][4];
  {
    int r = warp*16 + (lane & 7) + ((lane >> 3) & 1) * 8;
#pragma unroll
    for (int kc = 0; kc < 4; kc++){
      int ch = kc*2 + (lane >> 4);
      uint32_t ad = smb + FSM_Q + r*128 + ((ch ^ (r & 7)) * 16);
      LDSM4(qfh[kc][0], qfh[kc][1], qfh[kc][2], qfh[kc][3], ad);
      LDSM4(qfl[kc][0], qfl[kc][1], qfl[kc][2], qfl[kc][3], ad + 8192);
    }
  }

  float o[8][4];
#pragma unroll
  for (int nt=0;nt<8;nt++)
#pragma unroll
    for (int e=0;e<4;e++) o[nt][e] = 0.f;
  float m0r = -1e30f, m1r = -1e30f, l0 = 0.f, l1 = 0.f;

  const int r0g = qt*64 + warp*16 + g;
  const int r1g = r0g + 8;
  const int rBv = (lane & 7) + ((lane >> 4) << 3);
  const int chBv = (lane >> 3) & 1;
  const int rVv = (lane & 7) + (((lane >> 3) & 1) << 3);
  const int chVv = lane >> 4;

  for (int j = 0; j <= qt; j++){
    int s = j & 1;
    CPWAIT0();
    __syncthreads();
    if (j < qt){ stageKV(j + 1, s ^ 1); CPCOMMIT(); }

    const uint32_t kb = smb + FSM_KV + s*KV_STG;

    float sf[8][4];
#pragma unroll
    for (int nt=0;nt<8;nt++)
#pragma unroll
      for (int e=0;e<4;e++) sf[nt][e] = 0.f;

    // S = Q K^T (3-term split)
#pragma unroll
    for (int kc = 0; kc < 4; kc++){
#pragma unroll
      for (int ntp = 0; ntp < 4; ntp++){
        int r = ntp*16 + rBv;
        int ch = kc*2 + chBv;
        uint32_t ad = kb + r*128 + ((ch ^ (r & 7)) * 16);
        uint32_t bh0,bh1,bh2,bh3, bl0,bl1,bl2,bl3;
        LDSM4(bh0,bh1,bh2,bh3, ad);
        LDSM4(bl0,bl1,bl2,bl3, ad + 8192);
        MMA4(sf[2*ntp],   qfh[kc], bh0, bh1);
        MMA4(sf[2*ntp+1], qfh[kc], bh2, bh3);
        MMA4(sf[2*ntp],   qfh[kc], bl0, bl1);
        MMA4(sf[2*ntp+1], qfh[kc], bl2, bl3);
        MMA4(sf[2*ntp],   qfl[kc], bh0, bh1);
        MMA4(sf[2*ntp+1], qfl[kc], bh2, bh3);
      }
    }

    // online softmax
    float tm0 = -1e30f, tm1 = -1e30f;
#pragma unroll
    for (int nt = 0; nt < 8; nt++){
      int c0 = j*64 + nt*8 + 2*t;
      float v0 = sf[nt][0]*0.125f, v1 = sf[nt][1]*0.125f;
      float v2 = sf[nt][2]*0.125f, v3 = sf[nt][3]*0.125f;
      if (j == qt){
        if (c0     > r0g) v0 = -1e30f;
        if (c0 + 1 > r0g) v1 = -1e30f;
        if (c0     > r1g) v2 = -1e30f;
        if (c0 + 1 > r1g) v3 = -1e30f;
      }
      sf[nt][0]=v0; sf[nt][1]=v1; sf[nt][2]=v2; sf[nt][3]=v3;
      tm0 = fmaxf(tm0, fmaxf(v0, v1));
      tm1 = fmaxf(tm1, fmaxf(v2, v3));
    }
    tm0 = fmaxf(tm0, __shfl_xor_sync(0xffffffffu, tm0, 1));
    tm0 = fmaxf(tm0, __shfl_xor_sync(0xffffffffu, tm0, 2));
    tm1 = fmaxf(tm1, __shfl_xor_sync(0xffffffffu, tm1, 1));
    tm1 = fmaxf(tm1, __shfl_xor_sync(0xffffffffu, tm1, 2));

    float mn0 = fmaxf(m0r, tm0), mn1 = fmaxf(m1r, tm1);
    float corr0 = __expf(m0r - mn0), corr1 = __expf(m1r - mn1);
    float s0 = 0.f, s1 = 0.f;
#pragma unroll
    for (int nt = 0; nt < 8; nt++){
      sf[nt][0] = __expf(sf[nt][0] - mn0);
      sf[nt][1] = __expf(sf[nt][1] - mn0);
      sf[nt][2] = __expf(sf[nt][2] - mn1);
      sf[nt][3] = __expf(sf[nt][3] - mn1);
      s0 += sf[nt][0] + sf[nt][1];
      s1 += sf[nt][2] + sf[nt][3];
    }
    s0 += __shfl_xor_sync(0xffffffffu, s0, 1);
    s0 += __shfl_xor_sync(0xffffffffu, s0, 2);
    s1 += __shfl_xor_sync(0xffffffffu, s1, 1);
    s1 += __shfl_xor_sync(0xffffffffu, s1, 2);
    l0 = l0*corr0 + s0;  l1 = l1*corr1 + s1;
    m0r = mn0;  m1r = mn1;
#pragma unroll
    for (int nt = 0; nt < 8; nt++){
      o[nt][0] *= corr0; o[nt][1] *= corr0;
      o[nt][2] *= corr1; o[nt][3] *= corr1;
    }

    // O += P V  (3-term split; P packed C-frag -> A-frag in registers)
    const uint32_t vb = kb + 16384;
#pragma unroll
    for (int kc = 0; kc < 4; kc++){
      uint32_t ph[4], pl[4];
#pragma unroll
      for (int q2 = 0; q2 < 2; q2++){
        float c0 = sf[2*kc+q2][0], c1 = sf[2*kc+q2][1];
        float c2 = sf[2*kc+q2][2], c3 = sf[2*kc+q2][3];
        bf16 h0,h1,h2,h3, e0,e1,e2,e3;
        split1(c0,h0,e0); split1(c1,h1,e1); split1(c2,h2,e2); split1(c3,h3,e3);
        bf162 p01; p01.x=h0; p01.y=h1;  bf162 p23; p23.x=h2; p23.y=h3;
        bf162 q01; q01.x=e0; q01.y=e1;  bf162 q23; q23.x=e2; q23.y=e3;
        ph[2*q2 + 0] = *(uint32_t*)&p01;  ph[2*q2 + 1] = *(uint32_t*)&p23;
        pl[2*q2 + 0] = *(uint32_t*)&q01;  pl[2*q2 + 1] = *(uint32_t*)&q23;
      }
#pragma unroll
      for (int ntp = 0; ntp < 4; ntp++){
        int r = kc*16 + rVv;
        int ch = ntp*2 + chVv;
        uint32_t ad = vb + r*128 + ((ch ^ (r & 7)) * 16);
        uint32_t wh0,wh1,wh2,wh3, wl0,wl1,wl2,wl3;
        LDSM4T(wh0,wh1,wh2,wh3, ad);
        LDSM4T(wl0,wl1,wl2,wl3, ad + 8192);
        MMA4(o[2*ntp],   ph, wh0, wh1);
        MMA4(o[2*ntp+1], ph, wh2, wh3);
        MMA4(o[2*ntp],   ph, wl0, wl1);
        MMA4(o[2*ntp+1], ph, wl2, wl3);
        MMA4(o[2*ntp],   pl, wh0, wh1);
        MMA4(o[2*ntp+1], pl, wh2, wh3);
      }
    }
  }

  // epilogue: normalize, write split bf16 attn [b][l][h][d]
  float inv0 = 1.f / l0, inv1 = 1.f / l1;
  size_t ob0 = ((size_t)(b*Lc + qt*64 + warp*16 + g) * Hc + h) * HDc;
  size_t ob1 = ob0 + (size_t)8 * Hc * HDc;
#pragma unroll
  for (int nt = 0; nt < 8; nt++){
    int d = nt*8 + 2*t;
    float v0 = o[nt][0]*inv0, v1 = o[nt][1]*inv0;
    float v2 = o[nt][2]*inv1, v3 = o[nt][3]*inv1;
    bf16 h0,h1,h2,h3, e0,e1,e2,e3;
    split1(v0,h0,e0); split1(v1,h1,e1); split1(v2,h2,e2); split1(v3,h3,e3);
    bf162 a; a.x=h0; a.y=h1;  bf162 c; c.x=e0; c.y=e1;
    bf162 d2; d2.x=h2; d2.y=h3; bf162 f; f.x=e2; f.y=e3;
    *(bf162*)(Oh + ob0 + d) = a;  *(bf162*)(Ol + ob0 + d) = c;
    *(bf162*)(Oh + ob1 + d) = d2; *(bf162*)(Ol + ob1 + d) = f;
  }
}

// ---------------------------------------------------------------------------
extern "C" void kernel_launch(void* const* d_in, const int* in_sizes, int n_in,
                              void* d_out, int out_size)
{
  const float* x   = (const float*)d_in[0];
  const float* Wq  = (const float*)d_in[1];
  const float* Wk  = (const float*)d_in[2];
  const float* Wv  = (const float*)d_in[3];
  const float* Wo  = (const float*)d_in[4];
  const float* qnw = (const float*)d_in[5];
  const float* knw = (const float*)d_in[6];
  float* out = (float*)d_out;

  float *qlin, *klin, *vlin;
  bf16 *xh,*xl,*wqh,*wql,*wkh,*wkl,*wvh,*wvl,*woh,*wol;
  bf16 *qh,*ql,*kh,*kl,*vh,*vl,*ath,*atl;
  cudaGetSymbolAddress((void**)&qlin, g_qlin);
  cudaGetSymbolAddress((void**)&klin, g_klin);
  cudaGetSymbolAddress((void**)&vlin, g_vlin);
  cudaGetSymbolAddress((void**)&xh, g_xh);   cudaGetSymbolAddress((void**)&xl, g_xl);
  cudaGetSymbolAddress((void**)&wqh, g_wqT_h); cudaGetSymbolAddress((void**)&wql, g_wqT_l);
  cudaGetSymbolAddress((void**)&wkh, g_wkT_h); cudaGetSymbolAddress((void**)&wkl, g_wkT_l);
  cudaGetSymbolAddress((void**)&wvh, g_wvT_h); cudaGetSymbolAddress((void**)&wvl, g_wvT_l);
  cudaGetSymbolAddress((void**)&woh, g_woT_h); cudaGetSymbolAddress((void**)&wol, g_woT_l);
  cudaGetSymbolAddress((void**)&qh, g_qh); cudaGetSymbolAddress((void**)&ql, g_ql);
  cudaGetSymbolAddress((void**)&kh, g_kh); cudaGetSymbolAddress((void**)&kl, g_kl);
  cudaGetSymbolAddress((void**)&vh, g_vh); cudaGetSymbolAddress((void**)&vl, g_vl);
  cudaGetSymbolAddress((void**)&ath, g_ath); cudaGetSymbolAddress((void**)&atl, g_atl);

  const int M = Mtok;

  // converts
  splitx<<<(M*Dc/4 + 255)/256, 256>>>(x, xh, xl, M*Dc/4);
  wsplitT<<<dim3(Dc/32, Dc/32), dim3(32,8)>>>(Wq, wqh, wql, Dc, Hc*HDc);
  wsplitT<<<dim3((HKVc*HDc)/32, Dc/32), dim3(32,8)>>>(Wk, wkh, wkl, Dc, HKVc*HDc);
  wsplitT<<<dim3((HKVc*HDc)/32, Dc/32), dim3(32,8)>>>(Wv, wvh, wvl, Dc, HKVc*HDc);
  wsplitT<<<dim3(Dc/32, (Hc*HDc)/32), dim3(32,8)>>>(Wo, woh, wol, Hc*HDc, Dc);

  // projections
  cudaFuncSetAttribute(gemm_split, cudaFuncAttributeMaxDynamicSharedMemorySize, 131072);
  gemm_split<<<dim3((Hc*HDc)/128, M/128), 256, 131072>>>(xh, xl, wqh, wql, qlin, M, Hc*HDc, Dc);
  gemm_split<<<dim3((HKVc*HDc)/128, M/128), 256, 131072>>>(xh, xl, wkh, wkl, klin, M, HKVc*HDc, Dc);
  gemm_split<<<dim3((HKVc*HDc)/128, M/128), 256, 131072>>>(xh, xl, wvh, wvl, vlin, M, HKVc*HDc, Dc);

  // norm + rope + split (head-major)
  rmsrope_split<<<(M*Hc)/8, 256>>>(qlin, qnw, qh, ql, Hc, M*Hc);
  rmsrope_split<<<(M*HKVc)/8, 256>>>(klin, knw, kh, kl, HKVc, M*HKVc);
  vsplit_kernel<<<(M*HKVc)/8, 256>>>(vlin, vh, vl, M*HKVc);

  // flash attention
  cudaFuncSetAttribute(flash_tc, cudaFuncAttributeMaxDynamicSharedMemorySize, FLASH_SMEM);
  flash_tc<<<dim3(Lc/64, Hc, Bc), 128, FLASH_SMEM>>>(qh, ql, kh, kl, vh, vl, ath, atl);

  // output projection
  gemm_split<<<dim3(Dc/128, M/128), 256, 131072>>>(ath, atl, woh, wol, out, M, Dc, Dc);
}